// round 17
// baseline (speedup 1.0000x reference)
#include <cuda_runtime.h>

// DWTExtractor: 2-level Haar DWT + bilinear 2x upsample of level-2 details.
// Input:  (32, 1, 1024, 1024) fp32 -> Output: (32, 6, 512, 512) fp32
//          [cH1, cV1, cD1, up(cH2), up(cV2), up(cD2)]
//
// Champion geometry (FROZEN: 256 thr, lb(256,6), 32x32 tile, 4xLDG.128/cell,
// scalar Part 3, __stcs). R15 structure: 324 level-2 cells = 256 central
// (1/thread) + 68 halo (threads 0-67), ALL loads front-issued before any
// compute. Single change vs R15: input loads use __ldcg (L2-only, no L1
// allocation) -- the input has zero L1 reuse (each patch consumed once;
// halo reuse is cross-block, i.e. L2), so skipping L1 allocation frees
// l1tex bandwidth for Part 3's LDS and the merged phase's STS.
//   Halo clamping == jax resize weight renormalization at edges.
//   (one __syncthreads)
//   Part 3: scalar separable half-pixel bilinear (0.75/0.25), 4 outputs per
//   thread, float4 streaming stores.

#define TS    32
#define H2_T  18
#define H2_S  19

__global__ __launch_bounds__(256, 6)
void dwt_fused_kernel(const float* __restrict__ in, float* __restrict__ out)
{
    __shared__ float sH[H2_T * H2_S];
    __shared__ float sV[H2_T * H2_S];
    __shared__ float sD[H2_T * H2_S];

    const int b   = blockIdx.z;
    const int oy0 = blockIdx.y * TS;
    const int ox0 = blockIdx.x * TS;
    const int tid = threadIdx.x;

    const float* __restrict__ inb  = in  + (size_t)b * 1024 * 1024;
    float* __restrict__       outb = out + (size_t)b * 6 * 512 * 512;

    // per-channel float2 output bases (level-1 channels 0..2)
    float2* const oH = (float2*)outb;
    float2* const oV = oH + 131072;
    float2* const oD = oV + 131072;

    const int r0g = oy0 >> 1;   // level-2 tile origin on the 256-grid
    const int c0g = ox0 >> 1;

    // ---- Halo ring mapping (68 cells of the 18x18 grid) ----
    const bool has_halo = tid < 68;
    int hlr, hlc;
    if (tid < 18)       { hlr = 0;         hlc = tid;      }
    else if (tid < 36)  { hlr = 17;        hlc = tid - 18; }
    else if (tid < 52)  { hlr = tid - 35;  hlc = 0;        }
    else                { hlr = tid - 51;  hlc = 17;       }
    const int hr = min(max(r0g - 1 + hlr, 0), 255);   // clamp == jax renorm
    const int hc = min(max(c0g - 1 + hlc, 0), 255);

    // ---- Issue ALL loads up front: halo first, then central (__ldcg) ----
    float4 h0, h1, h2, h3;
    if (has_halo) {
        const float4* hp = (const float4*)(inb + (size_t)hr * 4096) + hc;
        h0 = __ldcg(hp);
        h1 = __ldcg(hp + 256);
        h2 = __ldcg(hp + 512);
        h3 = __ldcg(hp + 768);
    }

    // central cell: exactly one per thread (16x16 grid)
    const int crow = tid >> 4;          // 0..15
    const int ccol = tid & 15;          // 0..15
    const int rr = r0g + crow;          // in range, no clamp
    const int cc = c0g + ccol;
    const float4* p = (const float4*)(inb + (size_t)rr * 4096) + cc;
    const float4 v0 = __ldcg(p);
    const float4 v1 = __ldcg(p + 256);
    const float4 v2 = __ldcg(p + 512);
    const float4 v3 = __ldcg(p + 768);

    // ---- Halo compute first (data arrived first; frees registers) ----
    if (has_halo) {
        const float a00 = (h0.x + h0.y) + (h1.x + h1.y);
        const float a01 = (h0.z + h0.w) + (h1.z + h1.w);
        const float a10 = (h2.x + h2.y) + (h3.x + h3.y);
        const float a11 = (h2.z + h2.w) + (h3.z + h3.w);
        sH[hlr * H2_S + hlc] = (a00 - a01 + a10 - a11) * 0.25f;
        sV[hlr * H2_S + hlc] = (a00 + a01 - a10 - a11) * 0.25f;
        sD[hlr * H2_S + hlc] = (a00 - a01 - a10 + a11) * 0.25f;
    }

    // ---- Central compute: level-2 -> smem, level-1 2x2 block -> gmem ----
    {
        const float s0l = v0.x + v0.y, d0l = v0.x - v0.y;
        const float s0r = v0.z + v0.w, d0r = v0.z - v0.w;
        const float s1l = v1.x + v1.y, d1l = v1.x - v1.y;
        const float s1r = v1.z + v1.w, d1r = v1.z - v1.w;
        const float s2l = v2.x + v2.y, d2l = v2.x - v2.y;
        const float s2r = v2.z + v2.w, d2r = v2.z - v2.w;
        const float s3l = v3.x + v3.y, d3l = v3.x - v3.y;
        const float s3r = v3.z + v3.w, d3r = v3.z - v3.w;

        const float a00 = s0l + s1l, a01 = s0r + s1r;
        const float a10 = s2l + s3l, a11 = s2r + s3r;

        // level-2 coeffs: 0.5 (haar) * 0.5 (cA1 factor folded) = 0.25
        const int sidx = (crow + 1) * H2_S + (ccol + 1);
        sH[sidx] = (a00 - a01 + a10 - a11) * 0.25f;
        sV[sidx] = (a00 + a01 - a10 - a11) * 0.25f;
        sD[sidx] = (a00 - a01 - a10 + a11) * 0.25f;

        const float2 hT = make_float2((d0l + d1l) * 0.5f, (d0r + d1r) * 0.5f);
        const float2 vT = make_float2((s0l - s1l) * 0.5f, (s0r - s1r) * 0.5f);
        const float2 dT = make_float2((d0l - d1l) * 0.5f, (d0r - d1r) * 0.5f);
        const float2 hB = make_float2((d2l + d3l) * 0.5f, (d2r + d3r) * 0.5f);
        const float2 vB = make_float2((s2l - s3l) * 0.5f, (s2r - s3r) * 0.5f);
        const float2 dB = make_float2((d2l - d3l) * 0.5f, (d2r - d3r) * 0.5f);

        const int oT = rr * 512 + cc;        // float2 index
        const int oB = oT + 256;             // next output row
        __stcs(oH + oT, hT);
        __stcs(oH + oB, hB);
        __stcs(oV + oT, vT);
        __stcs(oV + oB, vB);
        __stcs(oD + oT, dT);
        __stcs(oD + oB, dB);
    }

    __syncthreads();

    // ---- Part 3: half-pixel bilinear 2x, 4 horizontally-adjacent outputs ----
    // out[2k] = 0.25*v[k-1]+0.75*v[k],  out[2k+1] = 0.75*v[k]+0.25*v[k+1]
    {
        const int y  = tid >> 3;       // 0..31
        const int xq = tid & 7;        // group of 4 cols
        const int ky = (y >> 1) + 1;   // local level-2 row of k
        const int ry0 = (y & 1) ? ky     : ky - 1;
        const int ry1 = (y & 1) ? ky + 1 : ky;
        const float wy0 = (y & 1) ? 0.75f : 0.25f;
        const float wy1 = 1.0f - wy0;

        const int cb = 2 * xq;         // local level-2 cols cb..cb+3 used
        const int A0 = ry0 * H2_S + cb;
        const int A1 = ry1 * H2_S + cb;

        float4 hv, vv, dv;
        {
            const float m0 = wy0 * sH[A0    ] + wy1 * sH[A1    ];
            const float m1 = wy0 * sH[A0 + 1] + wy1 * sH[A1 + 1];
            const float m2 = wy0 * sH[A0 + 2] + wy1 * sH[A1 + 2];
            const float m3 = wy0 * sH[A0 + 3] + wy1 * sH[A1 + 3];
            hv.x = 0.25f * m0 + 0.75f * m1;
            hv.y = 0.75f * m1 + 0.25f * m2;
            hv.z = 0.25f * m1 + 0.75f * m2;
            hv.w = 0.75f * m2 + 0.25f * m3;
        }
        {
            const float m0 = wy0 * sV[A0    ] + wy1 * sV[A1    ];
            const float m1 = wy0 * sV[A0 + 1] + wy1 * sV[A1 + 1];
            const float m2 = wy0 * sV[A0 + 2] + wy1 * sV[A1 + 2];
            const float m3 = wy0 * sV[A0 + 3] + wy1 * sV[A1 + 3];
            vv.x = 0.25f * m0 + 0.75f * m1;
            vv.y = 0.75f * m1 + 0.25f * m2;
            vv.z = 0.25f * m1 + 0.75f * m2;
            vv.w = 0.75f * m2 + 0.25f * m3;
        }
        {
            const float m0 = wy0 * sD[A0    ] + wy1 * sD[A1    ];
            const float m1 = wy0 * sD[A0 + 1] + wy1 * sD[A1 + 1];
            const float m2 = wy0 * sD[A0 + 2] + wy1 * sD[A1 + 2];
            const float m3 = wy0 * sD[A0 + 3] + wy1 * sD[A1 + 3];
            dv.x = 0.25f * m0 + 0.75f * m1;
            dv.y = 0.75f * m1 + 0.25f * m2;
            dv.z = 0.25f * m1 + 0.75f * m2;
            dv.w = 0.75f * m2 + 0.25f * m3;
        }

        float4* const u0 = (float4*)outb + 3 * 65536;
        const int o4 = ((oy0 + y) * 512 + ox0 + 4 * xq) >> 2;
        __stcs(u0 + o4,             hv);
        __stcs(u0 + 65536 + o4,     vv);
        __stcs(u0 + 2 * 65536 + o4, dv);
    }
}

extern "C" void kernel_launch(void* const* d_in, const int* in_sizes, int n_in,
                              void* d_out, int out_size)
{
    const float* x = (const float*)d_in[0];
    float* out = (float*)d_out;
    dim3 grid(512 / TS, 512 / TS, 32);   // (16, 16, 32) = 8192 blocks
    dwt_fused_kernel<<<grid, 256>>>(x, out);
}